// round 13
// baseline (speedup 1.0000x reference)
#include <cuda_runtime.h>

#define TPB    256
#define IPT    4            // consecutive sorted i's per thread
#define WIN    1024         // i-window granularity (== TPB*IPT)
#define JCH    256          // j-chunk width
#define MAXN   16384
#define NWARP  (TPB / 32)
#define MAXIW  (MAXN / WIN)     // 16
#define MAXJC  (MAXN / JCH)     // 64

// Device-global state. Statically zero on first (correctness) call; the
// finalizing block resets everything each launch -> identical state per replay.
__device__ unsigned long long g_C = 0ull, g_T = 0ull;
__device__ unsigned int g_M = 0u, g_done = 0u;
__device__ unsigned int g_iflag[MAXIW];          // zero-initialized
__device__ unsigned int g_jflag[MAXJC];
__device__ float2 g_is[MAXN];    // i windows, approx-sorted by y asc
__device__ float2 g_jc[MAXN];    // j chunks: compacted status==1, exact-sorted, +inf pad

__device__ __forceinline__ float pos_inf() { return __int_as_float(0x7f800000); }
__device__ __forceinline__ float neg_inf() { return __int_as_float(0xff800000); }

__device__ __forceinline__ unsigned int ldv(const unsigned int* p) {
    unsigned int v;
    asm volatile("ld.volatile.global.u32 %0, [%1];" : "=r"(v) : "l"(p));
    return v;
}

// 2-op accumulate: c += (yh >= b)
__device__ __forceinline__ void acc_ge(unsigned int& c, float yhv, float b) {
    asm volatile("{\n\t.reg .pred p;\n\t"
                 "setp.ge.f32 p, %1, %2;\n\t"
                 "@p add.u32 %0, %0, 1;\n\t}"
                 : "+r"(c) : "f"(yhv), "f"(b));
}
// 3-op guarded accumulate: c += (jj < len) && (yh >= b)
__device__ __forceinline__ void acc_ge_lt(unsigned int& c, int jj, int len,
                                          float yhv, float b) {
    asm volatile("{\n\t.reg .pred p, q;\n\t"
                 "setp.lt.s32 p, %1, %2;\n\t"
                 "setp.ge.and.f32 q, %3, %4, p;\n\t"
                 "@q add.u32 %0, %0, 1;\n\t}"
                 : "+r"(c) : "r"(jj), "r"(len), "f"(yhv), "f"(b));
}

// monotone 8-bit key from float (ascending)
__device__ __forceinline__ unsigned int key8(float f) {
    unsigned int u = __float_as_uint(f);
    u = (u >> 31) ? ~u : (u | 0x80000000u);
    return u >> 24;
}

union SmemU {
    struct {                               // i-window counting sort
        float2 sorted[WIN];                // 8KB
        unsigned int hist[256];
        unsigned int wsum[NWARP];
    } is;
    struct {                               // j-chunk rank sort
        float vy[JCH];
        float2 sorted[JCH];
    } js;
    struct {                               // pair path (syh 16B-aligned)
        float syc[JCH];
        float syh[JCH];
        unsigned long long sred[NWARP];
    } pr;
};

__global__ void __launch_bounds__(TPB, 4)
cindex_kernel(const float* __restrict__ y, const float* __restrict__ yh,
              const int* __restrict__ status, int n, float* __restrict__ out,
              int iwins, int jchunks, int half, int npair, int nprep) {
    __shared__ SmemU sm;
    const int tid = threadIdx.x;
    const int wid = tid >> 5, lid = tid & 31;
    const int b = (int)blockIdx.x;

    if (b < iwins) {
        // ===== i-window approximate counting sort (window b) =====
        const int base = b * WIN;
        float yv[IPT], yhv[IPT];
        unsigned int ky[IPT];
#pragma unroll
        for (int k = 0; k < IPT; k++) {
            int i = base + tid + k * TPB;
            bool v = (i < n);
            yv[k]  = v ? y[i]  : neg_inf();   // -inf pad -> len 0, harmless
            yhv[k] = v ? yh[i] : neg_inf();
            ky[k]  = key8(yv[k]);
        }
        sm.is.hist[tid] = 0u;
        __syncthreads();
#pragma unroll
        for (int k = 0; k < IPT; k++) atomicAdd(&sm.is.hist[ky[k]], 1u);
        __syncthreads();
        unsigned int cnt = sm.is.hist[tid];
        unsigned int incl = cnt;
#pragma unroll
        for (int off = 1; off < 32; off <<= 1) {
            unsigned int nb = __shfl_up_sync(0xffffffffu, incl, off);
            if (lid >= off) incl += nb;
        }
        if (lid == 31) sm.is.wsum[wid] = incl;
        __syncthreads();
        unsigned int wbase = 0;
#pragma unroll
        for (int w = 0; w < NWARP; w++) wbase += (w < wid) ? sm.is.wsum[w] : 0u;
        sm.is.hist[tid] = wbase + incl - cnt;   // exclusive offset, own bin only
        __syncthreads();
#pragma unroll
        for (int k = 0; k < IPT; k++) {
            unsigned int pos = atomicAdd(&sm.is.hist[ky[k]], 1u);
            sm.is.sorted[pos] = make_float2(yv[k], yhv[k]);
        }
        __syncthreads();
        for (int e = tid; e < WIN; e += TPB) g_is[base + e] = sm.is.sorted[e];
        __threadfence();
        __syncthreads();
        if (tid == 0) atomicExch(&g_iflag[b], 1u);
        return;
    }

    if (b < nprep) {
        // ===== j-chunk compact + exact rank-sort (chunk c) =====
        const int c = b - iwins;
        const int j = c * JCH + tid;
        const bool jv = (j < n);
        float yj  = jv ? y[j]  : 0.0f;
        float yhj = jv ? yh[j] : 0.0f;
        const bool keep = jv && (status[j] == 1);
        const float val = keep ? yj : pos_inf();
        sm.js.vy[tid] = val;
        unsigned int bal = __ballot_sync(0xffffffffu, keep);
        if (lid == 0 && bal) atomicAdd(&g_M, (unsigned int)__popc(bal));
        __syncthreads();
        int rank = 0;
        const float4* vy4 = reinterpret_cast<const float4*>(sm.js.vy);
#pragma unroll 4
        for (int q = 0; q < JCH / 4; q++) {
            float4 o = vy4[q];
            int k0 = q * 4;
            rank += (o.x < val) || (o.x == val && (k0 + 0) < tid);
            rank += (o.y < val) || (o.y == val && (k0 + 1) < tid);
            rank += (o.z < val) || (o.z == val && (k0 + 2) < tid);
            rank += (o.w < val) || (o.w == val && (k0 + 3) < tid);
        }
        sm.js.sorted[rank] = make_float2(val, keep ? yhj : pos_inf());
        __syncthreads();
        g_jc[c * JCH + tid] = sm.js.sorted[tid];
        __threadfence();
        __syncthreads();
        if (tid == 0) atomicExch(&g_jflag[c], 1u);
        return;
    }

    // ===== pair block: tiles (ixA, jy) and (ixB, jy), ixB = iwins-1-ixA =====
    const int pb  = b - nprep;
    const int ixA = pb % half;
    const int jy  = pb / half;
    const int ixB = iwins - 1 - ixA;

    if (tid == 0) {
        while (!ldv(&g_jflag[jy]))  __nanosleep(64);
        while (!ldv(&g_iflag[ixA])) __nanosleep(64);
        if (ixB > ixA) while (!ldv(&g_iflag[ixB])) __nanosleep(64);
        __threadfence();
    }
    __syncthreads();

    float2 vj = g_jc[jy * JCH + tid];
    sm.pr.syc[tid] = vj.x;
    sm.pr.syh[tid] = vj.y;
    __syncthreads();

    unsigned int tcnt = 0u, ccnt = 0u;
    const float4* syh4 = reinterpret_cast<const float4*>(sm.pr.syh);

#pragma unroll
    for (int t2 = 0; t2 < 2; t2++) {
        int ix = t2 ? ixB : ixA;
        if (t2 && ixB <= ixA) break;

        const int ib = ix * WIN + wid * (32 * IPT) + lid * IPT;
        float yi[IPT], yhi[IPT];
#pragma unroll
        for (int k = 0; k < IPT; k++) {
            float2 a = g_is[ib + k];
            yi[k] = a.x; yhi[k] = a.y;
        }

        // exact prefix lengths: #{j : yc_j <= y_i}; T += len
        int len[IPT];
#pragma unroll
        for (int k = 0; k < IPT; k++) {
            int l = 0;
#pragma unroll
            for (int s = 128; s; s >>= 1)
                if (sm.pr.syc[l + s - 1] <= yi[k]) l += s;
            len[k] = l;
            tcnt += (unsigned int)l;
        }
        int lmin = min(min(len[0], len[1]), min(len[2], len[3]));
        int lmax = max(max(len[0], len[1]), max(len[2], len[3]));

        // bulk: 1 LDS.128 + 32 predicate-ops per 16 pairs (yc implied)
        int nb4 = lmin >> 2;
        for (int q = 0; q < nb4; q++) {
            float4 b4 = syh4[q];
#pragma unroll
            for (int k = 0; k < IPT; k++) {
                acc_ge(ccnt, yhi[k], b4.x);
                acc_ge(ccnt, yhi[k], b4.y);
                acc_ge(ccnt, yhi[k], b4.z);
                acc_ge(ccnt, yhi[k], b4.w);
            }
        }
        // tail: remainder + lane spread, guarded by per-i len
        for (int jj = nb4 << 2; jj < lmax; jj++) {
            float bb = sm.pr.syh[jj];
#pragma unroll
            for (int k = 0; k < IPT; k++)
                acc_ge_lt(ccnt, jj, len[k], yhi[k], bb);
        }
    }

    // warp reduce, pack (t<<32 | c): block sums < 2^20, no carry
#pragma unroll
    for (int off = 16; off; off >>= 1) {
        tcnt += __shfl_down_sync(0xffffffffu, tcnt, off);
        ccnt += __shfl_down_sync(0xffffffffu, ccnt, off);
    }
    if (lid == 0)
        sm.pr.sred[wid] = ((unsigned long long)tcnt << 32) | (unsigned long long)ccnt;
    __syncthreads();

    if (tid == 0) {
        unsigned long long s = 0ull;
#pragma unroll
        for (int w = 0; w < NWARP; w++) s += sm.pr.sred[w];
        atomicAdd(&g_T, s >> 32);
        atomicAdd(&g_C, s & 0xffffffffull);
        __threadfence();
        unsigned int old = atomicAdd(&g_done, 1u);
        if (old == (unsigned int)(npair - 1)) {
            __threadfence();
            double M = (double)atomicAdd(&g_M, 0u);
            double c = (double)atomicAdd(&g_C, 0ull) - M;   // drop diagonal
            double t = (double)atomicAdd(&g_T, 0ull) - M;
            out[0] = (float)(c / t);
            // reset for next graph replay
            g_C = 0ull; g_T = 0ull; g_M = 0u; g_done = 0u;
            for (int w = 0; w < iwins; w++)   g_iflag[w] = 0u;
            for (int cc2 = 0; cc2 < jchunks; cc2++) g_jflag[cc2] = 0u;
        }
    }
}

extern "C" void kernel_launch(void* const* d_in, const int* in_sizes, int n_in,
                              void* d_out, int out_size) {
    const float* y      = (const float*)d_in[0];
    const float* yh     = (const float*)d_in[1];
    const int*   status = (const int*)d_in[2];
    int n = in_sizes[0];

    int iwins   = (n + WIN - 1) / WIN;     // 16
    int jchunks = (n + JCH - 1) / JCH;     // 64
    int half    = (iwins + 1) / 2;         // 8
    int nprep   = iwins + jchunks;         // 80
    int npair   = half * jchunks;          // 512

    cindex_kernel<<<nprep + npair, TPB>>>(y, yh, status, n, (float*)d_out,
                                          iwins, jchunks, half, npair, nprep);
}